// round 8
// baseline (speedup 1.0000x reference)
#include <cuda_runtime.h>
#include <cuda_bf16.h>
#include <math.h>

// ---------------- problem constants ----------------
#define DD   512
#define SS   3
#define BB   256
#define HH   8
#define HD_  64
#define TAYLOR_K 26

// ---------------- scratch (device globals; no allocation) ----------------
__device__ float g_h1pre [BB*DD];
__device__ float g_delta [BB];
__device__ float g_bx    [BB*DD];
__device__ float g_t0    [BB*DD];
__device__ float g_t1    [BB*DD];
__device__ float g_hssm  [BB*DD];
__device__ float g_gates [SS*BB*4*DD];
__device__ float g_q     [BB*DD];
__device__ float g_k     [SS*BB*DD];
__device__ float g_v     [SS*BB*DD];
__device__ float g_ctx   [BB*DD];
__device__ float g_fused [BB*DD];
__device__ float g_outpre[BB*DD];

// ---------------- helpers ----------------
__device__ __forceinline__ float warpAllReduceSum(float v) {
#pragma unroll
    for (int o = 16; o; o >>= 1) v += __shfl_xor_sync(0xffffffffu, v, o);
    return v;
}

// 256-thread block all-reduce (broadcast result)
__device__ __forceinline__ float blockAllReduceSum(float v, float* sbuf) {
    v = warpAllReduceSum(v);
    int w = threadIdx.x >> 5;
    if ((threadIdx.x & 31) == 0) sbuf[w] = v;
    __syncthreads();
    float r = 0.f;
#pragma unroll
    for (int i = 0; i < 8; i++) r += sbuf[i];
    __syncthreads();
    return r;
}

__device__ __forceinline__ float softplusf(float x) {
    return x > 0.f ? x + log1pf(expf(-x)) : log1pf(expf(x));
}
__device__ __forceinline__ float sigmf(float x) {
    return 1.f / (1.f + expf(-x));
}

// ---------------- generic GEMM: C[z] = rs(m)*rsmul * (A[z] @ B[z]^T) + bias, opt += C, opt Yacc += ----------------
// Tiles 32x32x32, 128 threads, each thread computes 4x2 outputs.
// All of M,N,K must be multiples of 32 (true for every call here).
__global__ __launch_bounds__(128) void gemm_nt_kernel(
    const float* __restrict__ A, int lda, long long aStr,
    const float* __restrict__ B, int ldb, long long bStr,
    float* __restrict__ C, int ldc, long long cStr,
    int K,
    const float* __restrict__ bias, int biasStr,
    const float* __restrict__ rowscale, float rsmul,
    float* __restrict__ Yacc,
    int accumulate)
{
    __shared__ float As[32][33];   // As[k][m]
    __shared__ float Bs[32][33];   // Bs[n][k]

    int z = blockIdx.z;
    A += (long long)z * aStr;
    B += (long long)z * bStr;
    C += (long long)z * cStr;

    int m0blk = blockIdx.y * 32;
    int n0blk = blockIdx.x * 32;
    int tid   = threadIdx.x;
    int kcol  = tid & 31;
    int rbase = tid >> 5;           // 0..3
    int tm = tid >> 4;              // 0..7
    int tn = tid & 15;              // 0..15
    int m0 = tm * 4, n0 = tn * 2;

    float acc[4][2] = {};

    const float* Ab = A + (long long)m0blk * lda;
    const float* Bb = B + (long long)n0blk * ldb;

    for (int kb = 0; kb < K; kb += 32) {
#pragma unroll
        for (int r = 0; r < 8; r++) {
            int row = rbase + r * 4;
            As[kcol][row] = Ab[(long long)row * lda + kb + kcol];
            Bs[row][kcol] = Bb[(long long)row * ldb + kb + kcol];
        }
        __syncthreads();
#pragma unroll
        for (int k = 0; k < 32; k++) {
            float a0 = As[k][m0 + 0];
            float a1 = As[k][m0 + 1];
            float a2 = As[k][m0 + 2];
            float a3 = As[k][m0 + 3];
            float b0 = Bs[n0 + 0][k];
            float b1 = Bs[n0 + 1][k];
            acc[0][0] += a0 * b0;  acc[0][1] += a0 * b1;
            acc[1][0] += a1 * b0;  acc[1][1] += a1 * b1;
            acc[2][0] += a2 * b0;  acc[2][1] += a2 * b1;
            acc[3][0] += a3 * b0;  acc[3][1] += a3 * b1;
        }
        __syncthreads();
    }

#pragma unroll
    for (int i = 0; i < 4; i++) {
        int gm = m0blk + m0 + i;
        float s = rowscale ? rowscale[gm] * rsmul : 1.f;
#pragma unroll
        for (int j = 0; j < 2; j++) {
            int gn = n0blk + n0 + j;
            float v = acc[i][j] * s;
            if (bias) v += bias[z * biasStr + gn];
            long long ci = (long long)gm * ldc + gn;
            if (accumulate) v += C[ci];
            C[ci] = v;
            if (Yacc) Yacc[(long long)gm * ldc + gn] += v;
        }
    }
}

// ---------------- LN -> gelu -> delta (one block per row, 256 thr) ----------------
__global__ __launch_bounds__(256) void ln_gelu_delta_kernel(
    const float* __restrict__ H,
    const float* __restrict__ g, const float* __restrict__ beta,
    const float* __restrict__ w2, const float* __restrict__ b2,
    float* __restrict__ delta)
{
    __shared__ float sbuf[8];
    int row = blockIdx.x;
    int t = threadIdx.x;
    const float* hr = H + row * DD;
    float x0 = hr[t], x1 = hr[t + 256];

    float s  = blockAllReduceSum(x0 + x1, sbuf);
    float ss = blockAllReduceSum(x0 * x0 + x1 * x1, sbuf);
    float mean = s * (1.f / DD);
    float var  = ss * (1.f / DD) - mean * mean;
    float inv  = rsqrtf(var + 1e-5f);

    float y0 = (x0 - mean) * inv * g[t]       + beta[t];
    float y1 = (x1 - mean) * inv * g[t + 256] + beta[t + 256];
    y0 = 0.5f * y0 * (1.f + erff(y0 * 0.70710678118654752f));
    y1 = 0.5f * y1 * (1.f + erff(y1 * 0.70710678118654752f));

    float d = blockAllReduceSum(y0 * w2[t] + y1 * w2[t + 256], sbuf);
    if (t == 0) delta[row] = softplusf(d + b2[0]);
}

// ---------------- final layernorm ----------------
__global__ __launch_bounds__(256) void ln_out_kernel(
    const float* __restrict__ H,
    const float* __restrict__ g, const float* __restrict__ beta,
    float* __restrict__ out)
{
    __shared__ float sbuf[8];
    int row = blockIdx.x;
    int t = threadIdx.x;
    const float* hr = H + row * DD;
    float x0 = hr[t], x1 = hr[t + 256];
    float s  = blockAllReduceSum(x0 + x1, sbuf);
    float ss = blockAllReduceSum(x0 * x0 + x1 * x1, sbuf);
    float mean = s * (1.f / DD);
    float var  = ss * (1.f / DD) - mean * mean;
    float inv  = rsqrtf(var + 1e-5f);
    out[row * DD + t]       = (x0 - mean) * inv * g[t]       + beta[t];
    out[row * DD + t + 256] = (x1 - mean) * inv * g[t + 256] + beta[t + 256];
}

// ---------------- SSM init: y = h_prev + delta*bx ; t0 = h_prev ----------------
__global__ void ssm_init_kernel(
    const float* __restrict__ h_prev, const float* __restrict__ delta,
    const float* __restrict__ bx, float* __restrict__ y, float* __restrict__ t0)
{
    int idx = blockIdx.x * blockDim.x + threadIdx.x;
    if (idx >= BB * DD) return;
    int row = idx >> 9;
    float hp = h_prev[idx];
    y[idx]  = hp + delta[row] * bx[idx];
    t0[idx] = hp;
}

// ---------------- LSTM elementwise ----------------
__global__ void lstm_elem_kernel(
    const float* __restrict__ gates, const float* __restrict__ c_in,
    const float* __restrict__ decays,
    float* __restrict__ h_out, float* __restrict__ c_out)
{
    int idx = blockIdx.x * blockDim.x + threadIdx.x;
    if (idx >= SS * BB * DD) return;
    int d  = idx & (DD - 1);
    int bs = idx >> 9;
    int s  = bs >> 8;
    const float* grow = gates + (long long)bs * (4 * DD);
    float i = sigmf(grow[d]);
    float f = sigmf(grow[DD + d]);
    float gg = tanhf(grow[2 * DD + d]);
    float o = sigmf(grow[3 * DD + d]);
    float c = c_in[idx];
    float craw = f * c + i * gg;
    float dec = decays[s];
    h_out[idx] = o * tanhf(craw);
    c_out[idx] = dec * c + (1.f - dec) * craw;
}

// ---------------- tiny attention: per (batch, head) softmax over S=3 ----------------
__global__ __launch_bounds__(256) void attn_kernel(
    const float* __restrict__ q, const float* __restrict__ k,
    const float* __restrict__ v, float* __restrict__ ctx)
{
    int b = blockIdx.x;
    int h = threadIdx.x >> 5;
    int l = threadIdx.x & 31;
    int e0 = h * HD_ + l;
    int e1 = e0 + 32;
    float q0 = q[b * DD + e0], q1 = q[b * DD + e1];

    float sc[SS];
#pragma unroll
    for (int s = 0; s < SS; s++) {
        const float* ks = k + ((long long)s * BB + b) * DD;
        float p = q0 * ks[e0] + q1 * ks[e1];
        p = warpAllReduceSum(p);
        sc[s] = p * 0.125f;   // 1/sqrt(64)
    }
    float m = fmaxf(sc[0], fmaxf(sc[1], sc[2]));
    float e[SS], sum = 0.f;
#pragma unroll
    for (int s = 0; s < SS; s++) { e[s] = expf(sc[s] - m); sum += e[s]; }
    float rinv = 1.f / sum;
    float c0 = 0.f, c1 = 0.f;
#pragma unroll
    for (int s = 0; s < SS; s++) {
        const float* vs = v + ((long long)s * BB + b) * DD;
        float a = e[s] * rinv;
        c0 += a * vs[e0];
        c1 += a * vs[e1];
    }
    ctx[b * DD + e0] = c0;
    ctx[b * DD + e1] = c1;
}

// ---------------- host launch ----------------
extern "C" void kernel_launch(void* const* d_in, const int* in_sizes, int n_in,
                              void* d_out, int out_size)
{
    const float* x        = (const float*)d_in[0];
    const float* h_prev   = (const float*)d_in[1];
    const float* lstm_h   = (const float*)d_in[2];
    const float* lstm_c   = (const float*)d_in[3];
    const float* Amat     = (const float*)d_in[4];
    const float* Bm       = (const float*)d_in[5];
    const float* dn_w1    = (const float*)d_in[6];
    const float* dn_b1    = (const float*)d_in[7];
    const float* dn_g     = (const float*)d_in[8];
    const float* dn_beta  = (const float*)d_in[9];
    const float* dn_w2    = (const float*)d_in[10];
    const float* dn_b2    = (const float*)d_in[11];
    const float* lstm_wih = (const float*)d_in[12];
    const float* lstm_whh = (const float*)d_in[13];
    const float* lstm_bih = (const float*)d_in[14];
    const float* lstm_bhh = (const float*)d_in[15];
    const float* decays   = (const float*)d_in[16];
    const float* attn_in_w= (const float*)d_in[17];
    const float* attn_in_b= (const float*)d_in[18];
    const float* attn_out_w=(const float*)d_in[19];
    const float* attn_out_b=(const float*)d_in[20];
    const float* proj_w   = (const float*)d_in[21];
    const float* proj_b   = (const float*)d_in[22];
    const float* proj_g   = (const float*)d_in[23];
    const float* proj_beta= (const float*)d_in[24];

    float* out = (float*)d_out;
    const long long OFF_HSSM = (long long)BB * DD;           // 131072
    const long long OFF_H    = 2 * OFF_HSSM;                 // 262144
    const long long OFF_C    = OFF_H + (long long)SS * BB * DD;

    float *h1pre, *delta, *bx, *t0, *t1, *hssm, *gates, *qb, *kb, *vb, *ctx, *fused, *outpre;
    cudaGetSymbolAddress((void**)&h1pre,  g_h1pre);
    cudaGetSymbolAddress((void**)&delta,  g_delta);
    cudaGetSymbolAddress((void**)&bx,     g_bx);
    cudaGetSymbolAddress((void**)&t0,     g_t0);
    cudaGetSymbolAddress((void**)&t1,     g_t1);
    cudaGetSymbolAddress((void**)&hssm,   g_hssm);
    cudaGetSymbolAddress((void**)&gates,  g_gates);
    cudaGetSymbolAddress((void**)&qb,     g_q);
    cudaGetSymbolAddress((void**)&kb,     g_k);
    cudaGetSymbolAddress((void**)&vb,     g_v);
    cudaGetSymbolAddress((void**)&ctx,    g_ctx);
    cudaGetSymbolAddress((void**)&fused,  g_fused);
    cudaGetSymbolAddress((void**)&outpre, g_outpre);

    dim3 blk(128);
    auto gemm = [&](const float* A, int lda, long long aStr,
                    const float* B, int ldb, long long bStr,
                    float* C, int ldc, long long cStr,
                    int M, int N, int K, int Z,
                    const float* bias, int biasStr,
                    const float* rs, float rsmul,
                    float* Yacc, int acc) {
        dim3 grid(N / 32, M / 32, Z);
        gemm_nt_kernel<<<grid, blk>>>(A, lda, aStr, B, ldb, bStr, C, ldc, cStr,
                                      K, bias, biasStr, rs, rsmul, Yacc, acc);
    };

    // 1) delta-net pre-LN GEMM
    gemm(x, DD, 0, dn_w1, DD, 0, h1pre, DD, 0, BB, DD, DD, 1,
         dn_b1, 0, nullptr, 0.f, nullptr, 0);
    // 2) LN + gelu + delta
    ln_gelu_delta_kernel<<<BB, 256>>>(h1pre, dn_g, dn_beta, dn_w2, dn_b2, delta);
    // 3) bx = x @ Bm^T
    gemm(x, DD, 0, Bm, DD, 0, bx, DD, 0, BB, DD, DD, 1,
         nullptr, 0, nullptr, 0.f, nullptr, 0);
    // 4) init: y = h_prev + delta*bx ; t0 = h_prev
    ssm_init_kernel<<<(BB * DD + 255) / 256, 256>>>(h_prev, delta, bx, hssm, t0);
    // 5) Taylor chain: t_k = (delta/k) * A @ t_{k-1}; y += t_k
    {
        float* tin = t0; float* tout = t1;
        for (int k = 1; k <= TAYLOR_K; k++) {
            gemm(tin, DD, 0, Amat, DD, 0, tout, DD, 0, BB, DD, DD, 1,
                 nullptr, 0, delta, 1.0f / (float)k, hssm, 0);
            float* tmp = tin; tin = tout; tout = tmp;
        }
    }
    // 6) LSTM gates pass 1: gates[s] = x @ wih[s]^T + bih[s]
    gemm(x, DD, 0, lstm_wih, DD, (long long)4 * DD * DD,
         gates, 4 * DD, (long long)BB * 4 * DD, BB, 4 * DD, DD, SS,
         lstm_bih, 4 * DD, nullptr, 0.f, nullptr, 0);
    // 7) pass 2: gates[s] += lstm_h[s] @ whh[s]^T + bhh[s]
    gemm(lstm_h, DD, (long long)BB * DD, lstm_whh, DD, (long long)4 * DD * DD,
         gates, 4 * DD, (long long)BB * 4 * DD, BB, 4 * DD, DD, SS,
         lstm_bhh, 4 * DD, nullptr, 0.f, nullptr, 1);
    // 8) LSTM elementwise -> h_new, c_new straight into d_out
    lstm_elem_kernel<<<(SS * BB * DD + 255) / 256, 256>>>(
        gates, lstm_c, decays, out + OFF_H, out + OFF_C);
    // 9) q = hssm @ Wq^T + bq
    gemm(hssm, DD, 0, attn_in_w, DD, 0, qb, DD, 0, BB, DD, DD, 1,
         attn_in_b, 0, nullptr, 0.f, nullptr, 0);
    // 10) k[s] = h_new[s] @ Wk^T + bk
    gemm(out + OFF_H, DD, (long long)BB * DD, attn_in_w + (long long)DD * DD, DD, 0,
         kb, DD, (long long)BB * DD, BB, DD, DD, SS,
         attn_in_b + DD, 0, nullptr, 0.f, nullptr, 0);
    // 11) v[s] = h_new[s] @ Wv^T + bv
    gemm(out + OFF_H, DD, (long long)BB * DD, attn_in_w + (long long)2 * DD * DD, DD, 0,
         vb, DD, (long long)BB * DD, BB, DD, DD, SS,
         attn_in_b + 2 * DD, 0, nullptr, 0.f, nullptr, 0);
    // 12) attention
    attn_kernel<<<BB, 256>>>(qb, kb, vb, ctx);
    // 13) fused = ctx @ attn_out_w^T + b
    gemm(ctx, DD, 0, attn_out_w, DD, 0, fused, DD, 0, BB, DD, DD, 1,
         attn_out_b, 0, nullptr, 0.f, nullptr, 0);
    // 14) proj: outpre = [hssm|fused|h0|h1|h2] @ proj_w^T + proj_b  (5 column-block GEMMs)
    {
        const float* parts[5] = { hssm, fused,
                                  out + OFF_H,
                                  out + OFF_H + (long long)BB * DD,
                                  out + OFF_H + (long long)2 * BB * DD };
        for (int j = 0; j < 5; j++) {
            gemm(parts[j], DD, 0, proj_w + (long long)j * DD, 5 * DD, 0,
                 outpre, DD, 0, BB, DD, DD, 1,
                 j == 0 ? proj_b : nullptr, 0, nullptr, 0.f, nullptr, j > 0 ? 1 : 0);
        }
    }
    // 15) final layernorm -> output
    ln_out_kernel<<<BB, 256>>>(outpre, proj_g, proj_beta, out);
    // 16) h_ssm -> d_out
    cudaMemcpyAsync(out + OFF_HSSM, hssm, (size_t)BB * DD * sizeof(float),
                    cudaMemcpyDeviceToDevice);
}